// round 1
// baseline (speedup 1.0000x reference)
#include <cuda_runtime.h>
#include <math.h>

// ---------------- problem constants ----------------
#define N1 3000
#define N2 2500
#define N3 2500
#define NTOT 8000
#define IN_F 128
#define OUT_F 64
#define HEADS 2
#define WORDS 250              // 8000 / 32 mask words per row

// attention tiling
#define TI 64                  // rows per block
#define TJ 64                  // cols per tile
#define NBLK_I (NTOT / TI)     // 125
#define NTILE_J (NTOT / TJ)    // 125

// ---------------- device scratch (static: no allocations allowed) ----------------
__device__ float    g_Wh[HEADS * NTOT * OUT_F];   // 4 MB
__device__ float    g_c [HEADS * NTOT];
__device__ float    g_s [HEADS * NTOT];
__device__ float    g_E1[HEADS * NTOT];
__device__ float    g_E2[HEADS * NTOT];
__device__ float    g_F1[HEADS * NTOT];
__device__ float    g_F2[HEADS * NTOT];
__device__ unsigned g_mask[NTOT * WORDS];         // 8 MB bitmask
__device__ float    g_x2[NTOT * HEADS * OUT_F];   // 4 MB

// ---------------- packed f32x2 helpers ----------------
static __device__ __forceinline__ unsigned long long dup2(float x) {
    float2 t = make_float2(x, x);
    unsigned long long r;
    asm("mov.b64 %0, {%1, %2};" : "=l"(r) : "f"(t.x), "f"(t.y));
    return r;
}
static __device__ __forceinline__ void fma2(unsigned long long &acc,
                                            unsigned long long a,
                                            unsigned long long b) {
    asm("fma.rn.f32x2 %0, %1, %2, %0;" : "+l"(acc) : "l"(a), "l"(b));
}
static __device__ __forceinline__ float2 upk(unsigned long long v) {
    float2 f;
    asm("mov.b64 {%0, %1}, %2;" : "=f"(f.x), "=f"(f.y) : "l"(v));
    return f;
}

// ---------------- kernel 1: Wh = h @ Ws  (per head) ----------------
__global__ void __launch_bounds__(256) k_wh(const float* __restrict__ h,
                                            const float* __restrict__ Ws) {
    int idx = blockIdx.x * 256 + threadIdx.x;     // [head*8000+n]*64 + o
    int o  = idx & 63;
    int nh = idx >> 6;
    int n  = nh % NTOT;
    int hd = nh / NTOT;
    const float* hp = h  + n * IN_F;
    const float* wp = Ws + hd * (IN_F * OUT_F) + o;
    float acc = 0.f;
#pragma unroll
    for (int f = 0; f < IN_F; ++f)
        acc = fmaf(hp[f], wp[f << 6], acc);
    g_Wh[idx] = acc;
}

// ---------------- kernel 2: per-node scalars ----------------
__global__ void __launch_bounds__(256) k_scal(const float* __restrict__ ap) {
    int idx = blockIdx.x * 256 + threadIdx.x;     // hd*8000 + i
    if (idx >= HEADS * NTOT) return;
    int hd = idx / NTOT;
    const float4* w  = (const float4*)(g_Wh + idx * OUT_F);
    const float4* a1 = (const float4*)(ap + hd * 2 * OUT_F);
    const float4* a2 = (const float4*)(ap + hd * 2 * OUT_F + OUT_F);
    float c = 0.f, s = 0.f;
#pragma unroll
    for (int k = 0; k < OUT_F / 4; ++k) {
        float4 v = w[k], x = a1[k], y = a2[k];
        c += v.x * x.x + v.y * x.y + v.z * x.z + v.w * x.w;
        s += v.x * y.x + v.y * y.y + v.z * y.z + v.w * y.w;
    }
    g_c[idx]  = c;
    g_s[idx]  = s;
    g_E1[idx] = __expf(c);
    g_E2[idx] = __expf(0.2f * c);
    g_F1[idx] = __expf(s);
    g_F2[idx] = __expf(0.2f * s);
}

// ---------------- kernel 3: pack block-mask into bitmask ----------------
static __device__ __forceinline__ int mask_val(
    int i, int j,
    const int* __restrict__ A1,  const int* __restrict__ A2,  const int* __restrict__ A3,
    const int* __restrict__ A12, const int* __restrict__ A13, const int* __restrict__ A23,
    const int* __restrict__ A21, const int* __restrict__ A31, const int* __restrict__ A32) {
    if (i < N1) {
        if (j < N1) return A1[i * N1 + j];
        if (j < N1 + N2) return A12[i * N2 + (j - N1)];
        return A13[i * N3 + (j - N1 - N2)];
    } else if (i < N1 + N2) {
        int ii = i - N1;
        if (j < N1) return A21[ii * N1 + j];
        if (j < N1 + N2) return A2[ii * N2 + (j - N1)];
        return A23[ii * N3 + (j - N1 - N2)];
    } else {
        int ii = i - N1 - N2;
        if (j < N1) return A31[ii * N1 + j];
        if (j < N1 + N2) return A32[ii * N2 + (j - N1)];
        return A3[ii * N3 + (j - N1 - N2)];
    }
}

__global__ void __launch_bounds__(256) k_maskpack(
    const int* __restrict__ A1,  const int* __restrict__ A2,  const int* __restrict__ A3,
    const int* __restrict__ A12, const int* __restrict__ A13, const int* __restrict__ A23,
    const int* __restrict__ A21, const int* __restrict__ A31, const int* __restrict__ A32) {
    int row  = blockIdx.x;
    int warp = threadIdx.x >> 5;
    int lane = threadIdx.x & 31;
    int j0   = warp << 10;                       // 1024 cols per warp
    unsigned myword = 0;
#pragma unroll 1
    for (int it = 0; it < 32; ++it) {
        int j = j0 + (it << 5) + lane;
        int m = (j < NTOT) ? mask_val(row, j, A1, A2, A3, A12, A13, A23, A21, A31, A32) : 0;
        unsigned b = __ballot_sync(0xffffffffu, m > 0);
        if (lane == it) myword = b;
    }
    int w = (j0 >> 5) + lane;
    if (w < WORDS) g_mask[row * WORDS + w] = myword;
}

// ---------------- kernel 4: fused masked-softmax attention + ELU ----------------
__global__ void __launch_bounds__(256) k_att() {
    __shared__ float sP [TJ][TI];      // attention weights (unnormalized), [j][i]
    __shared__ float sWh[TJ][OUT_F];   // value tile
    __shared__ float sD [4][TI];       // denominator partials

    const int head = blockIdx.y;
    const int hb   = head * NTOT;
    const int i0   = blockIdx.x * TI;
    const int tid  = threadIdx.x;

    // stage role: one (row, j-quarter) per thread
    const int sr = tid & 63;           // row in tile
    const int sq = tid >> 6;           // j-quarter (16 cols)
    const int bb = (sq & 1) * 16;      // bit base within mask word
    const float c_i = g_c [hb + i0 + sr];
    const float e1i = g_E1[hb + i0 + sr];
    const float e2i = g_E2[hb + i0 + sr];

    // compute role: 2 rows x 8 channels per thread
    const int chg  = tid & 7;          // channel group -> o = chg*8..chg*8+7
    const int rowg = tid >> 3;         // 0..31 -> rows rowg*2, rowg*2+1

    unsigned long long a00 = 0, a01 = 0, a02 = 0, a03 = 0;
    unsigned long long a10 = 0, a11 = 0, a12_ = 0, a13_ = 0;
    float dsum = 0.f;

    const unsigned* mrow = g_mask + (i0 + sr) * WORDS + (sq >> 1);

#pragma unroll 1
    for (int jt = 0; jt < NTILE_J; ++jt) {
        const int jbase = jt * TJ;
        __syncthreads();   // previous compute done before overwriting tiles

        // stage Wh tile: flat copy of 64x64 floats
        {
            const float4* src = (const float4*)(g_Wh + (hb + jbase) * OUT_F);
            float4* dst = (float4*)sWh;
#pragma unroll
            for (int e = tid; e < TJ * (OUT_F / 4); e += 256) dst[e] = src[e];
        }

        // stage P tile: p = mask * (c+s>=0 ? E1*F1 : E2*F2)
        {
            const unsigned wbits = mrow[jbase >> 5];
#pragma unroll
            for (int k = 0; k < 16; ++k) {
                const int jj = (sq << 4) + k;
                const int gj = hb + jbase + jj;
                const float sj = g_s [gj];
                const float f1 = g_F1[gj];
                const float f2 = g_F2[gj];
                float v = (c_i + sj >= 0.f) ? e1i * f1 : e2i * f2;
                float m = (float)((wbits >> (bb + k)) & 1u);
                float p = v * m;
                sP[jj][sr] = p;
                dsum += p;
            }
        }
        __syncthreads();

        // compute: rank-64 update, packed f32x2 FMA
#pragma unroll 4
        for (int j = 0; j < TJ; ++j) {
            const ulonglong2 wA = *(const ulonglong2*)(&sWh[j][chg * 8]);
            const ulonglong2 wB = *(const ulonglong2*)(&sWh[j][chg * 8 + 4]);
            const float2 p2 = *(const float2*)(&sP[j][rowg * 2]);
            const unsigned long long pa = dup2(p2.x);
            const unsigned long long pb = dup2(p2.y);
            fma2(a00, pa, wA.x); fma2(a01, pa, wA.y);
            fma2(a02, pa, wB.x); fma2(a03, pa, wB.y);
            fma2(a10, pb, wA.x); fma2(a11, pb, wA.y);
            fma2(a12_, pb, wB.x); fma2(a13_, pb, wB.y);
        }
    }

    // denominator reduce
    sD[sq][sr] = dsum;
    __syncthreads();

    // epilogue: normalize, ELU, write to x2 (head-concat layout)
#pragma unroll
    for (int r = 0; r < 2; ++r) {
        const int row = rowg * 2 + r;
        const float den = sD[0][row] + sD[1][row] + sD[2][row] + sD[3][row];
        const float inv = 1.f / den;
        float* op = g_x2 + (i0 + row) * (HEADS * OUT_F) + head * OUT_F + chg * 8;
        unsigned long long acc[4];
        if (r == 0) { acc[0] = a00; acc[1] = a01; acc[2] = a02; acc[3] = a03; }
        else        { acc[0] = a10; acc[1] = a11; acc[2] = a12_; acc[3] = a13_; }
#pragma unroll
        for (int m = 0; m < 4; ++m) {
            float2 v = upk(acc[m]);
            float x = v.x * inv, y = v.y * inv;
            x = (x > 0.f) ? x : expm1f(x);
            y = (y > 0.f) ? y : expm1f(y);
            op[2 * m]     = x;
            op[2 * m + 1] = y;
        }
    }
}

// ---------------- kernel 5: log_softmax (128-wide) + permuted row write ----------------
__global__ void __launch_bounds__(256) k_lsm(float* __restrict__ out) {
    const int lane = threadIdx.x & 31;
    const int i = blockIdx.x * 8 + (threadIdx.x >> 5);
    float4 v = ((const float4*)(g_x2 + i * 128))[lane];
    float mx = fmaxf(fmaxf(v.x, v.y), fmaxf(v.z, v.w));
#pragma unroll
    for (int off = 16; off > 0; off >>= 1)
        mx = fmaxf(mx, __shfl_xor_sync(0xffffffffu, mx, off));
    float sum = __expf(v.x - mx) + __expf(v.y - mx) + __expf(v.z - mx) + __expf(v.w - mx);
#pragma unroll
    for (int off = 16; off > 0; off >>= 1)
        sum += __shfl_xor_sync(0xffffffffu, sum, off);
    const float lse = mx + logf(sum);
    // output row order: (x3 rows 5500:8000) | (x4 rows 0:3000) | (x5 rows 3000:5500)
    const int orow = (i < N1 + N2) ? (i + N3) : (i - (N1 + N2));
    float4 o = make_float4(v.x - lse, v.y - lse, v.z - lse, v.w - lse);
    ((float4*)out)[orow * 32 + lane] = o;
}

// ---------------- launch ----------------
extern "C" void kernel_launch(void* const* d_in, const int* in_sizes, int n_in,
                              void* d_out, int out_size) {
    const float* h   = (const float*)d_in[0];
    const int*   A1  = (const int*)d_in[1];
    const int*   A2  = (const int*)d_in[2];
    const int*   A3  = (const int*)d_in[3];
    const int*   A12 = (const int*)d_in[4];
    const int*   A13 = (const int*)d_in[5];
    const int*   A23 = (const int*)d_in[6];
    const int*   A21 = (const int*)d_in[7];
    const int*   A31 = (const int*)d_in[8];
    const int*   A32 = (const int*)d_in[9];
    const float* Ws  = (const float*)d_in[10];
    const float* ap  = (const float*)d_in[11];

    k_wh<<<(HEADS * NTOT * OUT_F) / 256, 256>>>(h, Ws);
    k_scal<<<(HEADS * NTOT + 255) / 256, 256>>>(ap);
    k_maskpack<<<NTOT, 256>>>(A1, A2, A3, A12, A13, A23, A21, A31, A32);
    k_att<<<dim3(NBLK_I, HEADS), 256>>>();
    k_lsm<<<NTOT / 8, 256>>>((float*)d_out);
}

// round 2
// speedup vs baseline: 1.0607x; 1.0607x over previous
#include <cuda_runtime.h>
#include <math.h>

// ---------------- problem constants ----------------
#define N1 3000
#define N2 2500
#define N3 2500
#define NTOT 8000
#define IN_F 128
#define OUT_F 64
#define HEADS 2
#define WORDS 250              // 8000 / 32 mask words per row

// attention tiling
#define TI 64                  // rows per block
#define TJ 64                  // cols per tile
#define NBLK_I (NTOT / TI)     // 125
#define NTILE_J (NTOT / TJ)    // 125
#define KSPLIT 5
#define TILES_PER_SPLIT (NTILE_J / KSPLIT)   // 25

// ---------------- device scratch (static: no allocations allowed) ----------------
__device__ float    g_Wh[HEADS * NTOT * OUT_F];   // 4 MB
__device__ float    g_c [HEADS * NTOT];
__device__ float    g_s [HEADS * NTOT];
__device__ float    g_E1[HEADS * NTOT];
__device__ float    g_E2[HEADS * NTOT];
__device__ float    g_F1[HEADS * NTOT];
__device__ float    g_F2[HEADS * NTOT];
__device__ unsigned g_mask[NTOT * WORDS];         // 8 MB bitmask
__device__ float    g_x2[NTOT * HEADS * OUT_F];   // 4 MB
__device__ float    g_midp[KSPLIT * HEADS * NTOT * OUT_F];  // 20 MB partial mid
__device__ float    g_denp[KSPLIT * HEADS * NTOT];          // partial denominators

// ---------------- packed f32x2 helpers ----------------
static __device__ __forceinline__ void fma2(unsigned long long &acc,
                                            unsigned long long a,
                                            unsigned long long b) {
    asm("fma.rn.f32x2 %0, %1, %2, %0;" : "+l"(acc) : "l"(a), "l"(b));
}
static __device__ __forceinline__ float2 upk(unsigned long long v) {
    float2 f;
    asm("mov.b64 {%0, %1}, %2;" : "=f"(f.x), "=f"(f.y) : "l"(v));
    return f;
}

// ---------------- kernel 1: Wh = h @ Ws  (per head) ----------------
__global__ void __launch_bounds__(256) k_wh(const float* __restrict__ h,
                                            const float* __restrict__ Ws) {
    int idx = blockIdx.x * 256 + threadIdx.x;     // [head*8000+n]*64 + o
    int o  = idx & 63;
    int nh = idx >> 6;
    int n  = nh % NTOT;
    int hd = nh / NTOT;
    const float* hp = h  + n * IN_F;
    const float* wp = Ws + hd * (IN_F * OUT_F) + o;
    float acc = 0.f;
#pragma unroll
    for (int f = 0; f < IN_F; ++f)
        acc = fmaf(hp[f], wp[f << 6], acc);
    g_Wh[idx] = acc;
}

// ---------------- kernel 2: per-node scalars ----------------
__global__ void __launch_bounds__(256) k_scal(const float* __restrict__ ap) {
    int idx = blockIdx.x * 256 + threadIdx.x;     // hd*8000 + i
    if (idx >= HEADS * NTOT) return;
    int hd = idx / NTOT;
    const float4* w  = (const float4*)(g_Wh + idx * OUT_F);
    const float4* a1 = (const float4*)(ap + hd * 2 * OUT_F);
    const float4* a2 = (const float4*)(ap + hd * 2 * OUT_F + OUT_F);
    float c = 0.f, s = 0.f;
#pragma unroll
    for (int k = 0; k < OUT_F / 4; ++k) {
        float4 v = w[k], x = a1[k], y = a2[k];
        c += v.x * x.x + v.y * x.y + v.z * x.z + v.w * x.w;
        s += v.x * y.x + v.y * y.y + v.z * y.z + v.w * y.w;
    }
    g_c[idx]  = c;
    g_s[idx]  = s;
    g_E1[idx] = __expf(c);
    g_E2[idx] = __expf(0.2f * c);
    g_F1[idx] = __expf(s);
    g_F2[idx] = __expf(0.2f * s);
}

// ---------------- kernel 3: pack block-mask into bitmask ----------------
static __device__ __forceinline__ int mask_val(
    int i, int j,
    const int* __restrict__ A1,  const int* __restrict__ A2,  const int* __restrict__ A3,
    const int* __restrict__ A12, const int* __restrict__ A13, const int* __restrict__ A23,
    const int* __restrict__ A21, const int* __restrict__ A31, const int* __restrict__ A32) {
    if (i < N1) {
        if (j < N1) return A1[i * N1 + j];
        if (j < N1 + N2) return A12[i * N2 + (j - N1)];
        return A13[i * N3 + (j - N1 - N2)];
    } else if (i < N1 + N2) {
        int ii = i - N1;
        if (j < N1) return A21[ii * N1 + j];
        if (j < N1 + N2) return A2[ii * N2 + (j - N1)];
        return A23[ii * N3 + (j - N1 - N2)];
    } else {
        int ii = i - N1 - N2;
        if (j < N1) return A31[ii * N1 + j];
        if (j < N1 + N2) return A32[ii * N2 + (j - N1)];
        return A3[ii * N3 + (j - N1 - N2)];
    }
}

__global__ void __launch_bounds__(256) k_maskpack(
    const int* __restrict__ A1,  const int* __restrict__ A2,  const int* __restrict__ A3,
    const int* __restrict__ A12, const int* __restrict__ A13, const int* __restrict__ A23,
    const int* __restrict__ A21, const int* __restrict__ A31, const int* __restrict__ A32) {
    int row  = blockIdx.x;
    int warp = threadIdx.x >> 5;
    int lane = threadIdx.x & 31;
    int j0   = warp << 10;                       // 1024 cols per warp
    unsigned myword = 0;
#pragma unroll 1
    for (int it = 0; it < 32; ++it) {
        int j = j0 + (it << 5) + lane;
        int m = (j < NTOT) ? mask_val(row, j, A1, A2, A3, A12, A13, A23, A21, A31, A32) : 0;
        unsigned b = __ballot_sync(0xffffffffu, m > 0);
        if (lane == it) myword = b;
    }
    int w = (j0 >> 5) + lane;
    if (w < WORDS) g_mask[row * WORDS + w] = myword;
}

// ---------------- kernel 4: masked-softmax attention partials ----------------
// grid: (125, 2*KSPLIT); block 256.  Each block: 64 rows x 64 chans, 25 j-tiles.
__global__ void __launch_bounds__(256) k_att() {
    __shared__ float sPd[TJ][2 * TI];   // duplicated P: sPd[j][2i]=sPd[j][2i+1]=p_ij (32KB)
    __shared__ float sWh[TJ][OUT_F];    // value tile (16KB)

    const int head  = blockIdx.y & 1;
    const int split = blockIdx.y >> 1;
    const int hb    = head * NTOT;
    const int i0    = blockIdx.x * TI;
    const int tid   = threadIdx.x;

    // stage role: one (row, j-quarter) per thread
    const int sr = tid & 63;           // row in tile
    const int sq = tid >> 6;           // j-quarter (16 cols)
    const int bb = (sq & 1) * 16;      // bit base within mask word
    const float c_i = g_c [hb + i0 + sr];
    const float e1i = g_E1[hb + i0 + sr];
    const float e2i = g_E2[hb + i0 + sr];

    // compute role: 2 rows x 8 channels per thread
    const int chg  = tid & 7;          // channel group -> o = chg*8..chg*8+7
    const int rowg = tid >> 3;         // 0..31 -> rows rowg*2, rowg*2+1

    unsigned long long a00 = 0, a01 = 0, a02 = 0, a03 = 0;
    unsigned long long a10 = 0, a11 = 0, a12_ = 0, a13_ = 0;
    float dsum = 0.f;

    const unsigned* mrow = g_mask + (i0 + sr) * WORDS + (sq >> 1);
    const int t0 = split * TILES_PER_SPLIT;

#pragma unroll 1
    for (int jt = t0; jt < t0 + TILES_PER_SPLIT; ++jt) {
        const int jbase = jt * TJ;
        __syncthreads();   // previous compute done before overwriting tiles

        // stage Wh tile: flat copy of 64x64 floats
        {
            const float4* src = (const float4*)(g_Wh + (hb + jbase) * OUT_F);
            float4* dst = (float4*)sWh;
#pragma unroll
            for (int e = tid; e < TJ * (OUT_F / 4); e += 256) dst[e] = src[e];
        }

        // stage P tile (duplicated): p = mask * (c+s>=0 ? E1*F1 : E2*F2)
        {
            const unsigned wbits = mrow[jbase >> 5];
#pragma unroll
            for (int k = 0; k < 16; ++k) {
                const int jj = (sq << 4) + k;
                const int gj = hb + jbase + jj;
                const float sj = g_s [gj];
                const float f1 = g_F1[gj];
                const float f2 = g_F2[gj];
                float v = (c_i + sj >= 0.f) ? e1i * f1 : e2i * f2;
                float p = ((wbits >> (bb + k)) & 1u) ? v : 0.f;
                *(float2*)(&sPd[jj][sr * 2]) = make_float2(p, p);
                dsum += p;
            }
        }
        __syncthreads();

        // compute: rank-64 update, packed f32x2 FMA
#pragma unroll 4
        for (int j = 0; j < TJ; ++j) {
            const ulonglong2 wA = *(const ulonglong2*)(&sWh[j][chg * 8]);
            const ulonglong2 wB = *(const ulonglong2*)(&sWh[j][chg * 8 + 4]);
            const ulonglong2 pv = *(const ulonglong2*)(&sPd[j][rowg * 4]); // {p0,p0},{p1,p1}
            fma2(a00, pv.x, wA.x); fma2(a01, pv.x, wA.y);
            fma2(a02, pv.x, wB.x); fma2(a03, pv.x, wB.y);
            fma2(a10, pv.y, wA.x); fma2(a11, pv.y, wA.y);
            fma2(a12_, pv.y, wB.x); fma2(a13_, pv.y, wB.y);
        }
    }

    // denominator reduce (reuse sPd memory as scratch)
    __syncthreads();
    float* sD = &sPd[0][0];            // [4][64]
    sD[sq * 64 + sr] = dsum;
    __syncthreads();

    // epilogue: write raw partial accumulators + partial denominators
    const int pb = (split * HEADS + head) * NTOT;
#pragma unroll
    for (int r = 0; r < 2; ++r) {
        const int row = rowg * 2 + r;
        float* op = g_midp + (pb + i0 + row) * OUT_F + chg * 8;
        unsigned long long acc[4];
        if (r == 0) { acc[0] = a00; acc[1] = a01; acc[2] = a02; acc[3] = a03; }
        else        { acc[0] = a10; acc[1] = a11; acc[2] = a12_; acc[3] = a13_; }
#pragma unroll
        for (int m = 0; m < 4; ++m) {
            float2 v = upk(acc[m]);
            ((float2*)op)[m] = v;
        }
        if (chg == 0) {
            const float den = sD[row] + sD[64 + row] + sD[128 + row] + sD[192 + row];
            g_denp[pb + i0 + row] = den;
        }
    }
}

// ---------------- kernel 4b: combine splits, normalize, ELU ----------------
__global__ void __launch_bounds__(256) k_fin() {
    const int t = blockIdx.x * 256 + threadIdx.x;   // [head][i][o]
    const int o    = t & 63;
    const int i    = (t >> 6) % NTOT;
    const int head = t / (NTOT * OUT_F);
    float mid = 0.f, den = 0.f;
#pragma unroll
    for (int s = 0; s < KSPLIT; ++s) {
        const int pb = (s * HEADS + head) * NTOT + i;
        mid += g_midp[pb * OUT_F + o];
        den += g_denp[pb];
    }
    float x = mid / den;
    x = (x > 0.f) ? x : expm1f(x);
    g_x2[i * (HEADS * OUT_F) + head * OUT_F + o] = x;
}

// ---------------- kernel 5: log_softmax (128-wide) + permuted row write ----------------
__global__ void __launch_bounds__(256) k_lsm(float* __restrict__ out) {
    const int lane = threadIdx.x & 31;
    const int i = blockIdx.x * 8 + (threadIdx.x >> 5);
    float4 v = ((const float4*)(g_x2 + i * 128))[lane];
    float mx = fmaxf(fmaxf(v.x, v.y), fmaxf(v.z, v.w));
#pragma unroll
    for (int off = 16; off > 0; off >>= 1)
        mx = fmaxf(mx, __shfl_xor_sync(0xffffffffu, mx, off));
    float sum = __expf(v.x - mx) + __expf(v.y - mx) + __expf(v.z - mx) + __expf(v.w - mx);
#pragma unroll
    for (int off = 16; off > 0; off >>= 1)
        sum += __shfl_xor_sync(0xffffffffu, sum, off);
    const float lse = mx + logf(sum);
    // output row order: (x3 rows 5500:8000) | (x4 rows 0:3000) | (x5 rows 3000:5500)
    const int orow = (i < N1 + N2) ? (i + N3) : (i - (N1 + N2));
    float4 o = make_float4(v.x - lse, v.y - lse, v.z - lse, v.w - lse);
    ((float4*)out)[orow * 32 + lane] = o;
}

// ---------------- launch ----------------
extern "C" void kernel_launch(void* const* d_in, const int* in_sizes, int n_in,
                              void* d_out, int out_size) {
    const float* h   = (const float*)d_in[0];
    const int*   A1  = (const int*)d_in[1];
    const int*   A2  = (const int*)d_in[2];
    const int*   A3  = (const int*)d_in[3];
    const int*   A12 = (const int*)d_in[4];
    const int*   A13 = (const int*)d_in[5];
    const int*   A23 = (const int*)d_in[6];
    const int*   A21 = (const int*)d_in[7];
    const int*   A31 = (const int*)d_in[8];
    const int*   A32 = (const int*)d_in[9];
    const float* Ws  = (const float*)d_in[10];
    const float* ap  = (const float*)d_in[11];

    k_wh<<<(HEADS * NTOT * OUT_F) / 256, 256>>>(h, Ws);
    k_scal<<<(HEADS * NTOT + 255) / 256, 256>>>(ap);
    k_maskpack<<<NTOT, 256>>>(A1, A2, A3, A12, A13, A23, A21, A31, A32);
    k_att<<<dim3(NBLK_I, HEADS * KSPLIT), 256>>>();
    k_fin<<<(HEADS * NTOT * OUT_F) / 256, 256>>>();
    k_lsm<<<NTOT / 8, 256>>>((float*)d_out);
}

// round 3
// speedup vs baseline: 1.3785x; 1.2995x over previous
#include <cuda_runtime.h>
#include <math.h>

// ---------------- problem constants ----------------
#define N1 3000
#define N2 2500
#define N3 2500
#define NTOT 8000
#define NPAD 8192
#define IN_F 128
#define OUT_F 64
#define HEADS 2
#define WORDS 250              // 8000 / 32 mask words per row

// attention tiling
#define TI 256                 // rows per block
#define TJ 64                  // cols per tile
#define IBLK (NPAD / TI)       // 32
#define NTILE_J (NTOT / TJ)    // 125
#define KSPLIT 4

// ---------------- device scratch (static: no allocations allowed) ----------------
__device__ float    g_Wh[HEADS * NPAD * OUT_F];
__device__ float    g_c [HEADS * NPAD];
__device__ float    g_s [HEADS * NPAD];
__device__ float    g_E1[HEADS * NPAD];
__device__ float    g_E2[HEADS * NPAD];
__device__ float    g_F1[HEADS * NPAD];
__device__ float    g_F2[HEADS * NPAD];
__device__ unsigned g_mask[NPAD * WORDS];
__device__ float    g_x2[NTOT * HEADS * OUT_F];
__device__ float    g_midp[KSPLIT * HEADS * NPAD * OUT_F];
__device__ float    g_denp[KSPLIT * HEADS * NPAD];

// ---------------- packed f32x2 helpers ----------------
static __device__ __forceinline__ unsigned long long dup2(float x) {
    unsigned long long r;
    asm("mov.b64 %0, {%1, %2};" : "=l"(r) : "f"(x), "f"(x));
    return r;
}
static __device__ __forceinline__ void fma2(unsigned long long &acc,
                                            unsigned long long a,
                                            unsigned long long b) {
    asm("fma.rn.f32x2 %0, %1, %2, %0;" : "+l"(acc) : "l"(a), "l"(b));
}
static __device__ __forceinline__ float2 upk(unsigned long long v) {
    float2 f;
    asm("mov.b64 {%0, %1}, %2;" : "=f"(f.x), "=f"(f.y) : "l"(v));
    return f;
}

// ---------------- kernel 1: Wh = h @ Ws  (per head) ----------------
__global__ void __launch_bounds__(256) k_wh(const float* __restrict__ h,
                                            const float* __restrict__ Ws) {
    int idx = blockIdx.x * 256 + threadIdx.x;     // [head][n][o] over real rows
    int o  = idx & 63;
    int nh = idx >> 6;
    int n  = nh % NTOT;
    int hd = nh / NTOT;
    const float* hp = h  + n * IN_F;
    const float* wp = Ws + hd * (IN_F * OUT_F) + o;
    float acc = 0.f;
#pragma unroll
    for (int f = 0; f < IN_F; ++f)
        acc = fmaf(hp[f], wp[f << 6], acc);
    g_Wh[(hd * NPAD + n) * OUT_F + o] = acc;
}

// ---------------- kernel 2: per-node scalars ----------------
__global__ void __launch_bounds__(256) k_scal(const float* __restrict__ ap) {
    int idx = blockIdx.x * 256 + threadIdx.x;     // hd*NTOT + i (real rows)
    if (idx >= HEADS * NTOT) return;
    int hd = idx / NTOT;
    int i  = idx % NTOT;
    int g  = hd * NPAD + i;
    const float4* w  = (const float4*)(g_Wh + g * OUT_F);
    const float4* a1 = (const float4*)(ap + hd * 2 * OUT_F);
    const float4* a2 = (const float4*)(ap + hd * 2 * OUT_F + OUT_F);
    float c = 0.f, s = 0.f;
#pragma unroll
    for (int k = 0; k < OUT_F / 4; ++k) {
        float4 v = w[k], x = a1[k], y = a2[k];
        c += v.x * x.x + v.y * x.y + v.z * x.z + v.w * x.w;
        s += v.x * y.x + v.y * y.y + v.z * y.z + v.w * y.w;
    }
    g_c[g]  = c;
    g_s[g]  = s;
    g_E1[g] = __expf(c);
    g_E2[g] = __expf(0.2f * c);
    g_F1[g] = __expf(s);
    g_F2[g] = __expf(0.2f * s);
}

// ---------------- kernel 3: pack block-mask into bitmask ----------------
static __device__ __forceinline__ int mask_val(
    int i, int j,
    const int* __restrict__ A1,  const int* __restrict__ A2,  const int* __restrict__ A3,
    const int* __restrict__ A12, const int* __restrict__ A13, const int* __restrict__ A23,
    const int* __restrict__ A21, const int* __restrict__ A31, const int* __restrict__ A32) {
    if (i < N1) {
        if (j < N1) return A1[i * N1 + j];
        if (j < N1 + N2) return A12[i * N2 + (j - N1)];
        return A13[i * N3 + (j - N1 - N2)];
    } else if (i < N1 + N2) {
        int ii = i - N1;
        if (j < N1) return A21[ii * N1 + j];
        if (j < N1 + N2) return A2[ii * N2 + (j - N1)];
        return A23[ii * N3 + (j - N1 - N2)];
    } else {
        int ii = i - N1 - N2;
        if (j < N1) return A31[ii * N1 + j];
        if (j < N1 + N2) return A32[ii * N2 + (j - N1)];
        return A3[ii * N3 + (j - N1 - N2)];
    }
}

__global__ void __launch_bounds__(256) k_maskpack(
    const int* __restrict__ A1,  const int* __restrict__ A2,  const int* __restrict__ A3,
    const int* __restrict__ A12, const int* __restrict__ A13, const int* __restrict__ A23,
    const int* __restrict__ A21, const int* __restrict__ A31, const int* __restrict__ A32) {
    int row  = blockIdx.x;
    int warp = threadIdx.x >> 5;
    int lane = threadIdx.x & 31;
    int j0   = warp << 10;                       // 1024 cols per warp
    unsigned myword = 0;
#pragma unroll 1
    for (int it = 0; it < 32; ++it) {
        int j = j0 + (it << 5) + lane;
        int m = (j < NTOT) ? mask_val(row, j, A1, A2, A3, A12, A13, A23, A21, A31, A32) : 0;
        unsigned b = __ballot_sync(0xffffffffu, m > 0);
        if (lane == it) myword = b;
    }
    int w = (j0 >> 5) + lane;
    if (w < WORDS) g_mask[row * WORDS + w] = myword;
}

// ---------------- kernel 4: masked-softmax attention partials ----------------
// grid (IBLK, HEADS*KSPLIT), 256 threads. Block tile: 256 rows x 64 chans.
// Thread tile: 8 rows x 8 chans (split 4+4 with 128/32 offset for conflict-free LDS.128).
__global__ void __launch_bounds__(256, 2) k_att() {
    extern __shared__ float smem[];
    float* sP  = smem;               // [TJ][TI]  64KB
    float* sWh = smem + TJ * TI;     // [TJ][OUT_F] 16KB

    const int head  = blockIdx.y & 1;
    const int split = blockIdx.y >> 1;
    const int hb    = head * NPAD;
    const int i0    = blockIdx.x * TI;
    const int tid   = threadIdx.x;

    // p-gen role: this thread owns row i0+tid
    const float c_i = g_c [hb + i0 + tid];
    const float e1i = g_E1[hb + i0 + tid];
    const float e2i = g_E2[hb + i0 + tid];
    const unsigned* mrow = g_mask + (i0 + tid) * WORDS;

    // compute role
    const int cg = tid & 7;
    const int rg = tid >> 3;
    const int cA = cg * 4, cB = 32 + cg * 4;
    const int rA = rg * 4, rB = 128 + rg * 4;

    unsigned long long acc[8][4];
#pragma unroll
    for (int r = 0; r < 8; ++r)
#pragma unroll
        for (int q = 0; q < 4; ++q) acc[r][q] = 0ull;
    float dsum = 0.f;

    const int t0 = (split * NTILE_J) / KSPLIT;
    const int t1 = ((split + 1) * NTILE_J) / KSPLIT;

#pragma unroll 1
    for (int jt = t0; jt < t1; ++jt) {
        const int jbase = jt * TJ;
        __syncthreads();   // previous compute done before overwriting tiles

        // stage Wh tile: 1024 float4, 4 per thread
        {
            const float4* src = (const float4*)(g_Wh + (hb + jbase) * OUT_F);
            float4* dst = (float4*)sWh;
#pragma unroll
            for (int e = 0; e < 4; ++e) dst[tid + 256 * e] = src[tid + 256 * e];
        }

        // p-gen: this thread fills column i=tid of sP for all 64 j
        {
            const unsigned m0 = mrow[(jbase >> 5)];
            const unsigned m1 = mrow[(jbase >> 5) + 1];
            const float* sj  = g_s  + hb + jbase;
            const float* f1j = g_F1 + hb + jbase;
            const float* f2j = g_F2 + hb + jbase;
#pragma unroll
            for (int k = 0; k < 64; ++k) {
                const unsigned bit = (k < 32) ? (m0 >> k) : (m1 >> (k - 32));
                const float v = (c_i + sj[k] >= 0.f) ? e1i * f1j[k] : e2i * f2j[k];
                const float p = (bit & 1u) ? v : 0.f;
                sP[k * TI + tid] = p;
                dsum += p;
            }
        }
        __syncthreads();

        // compute: rank-64 update, 8x8 register tile, packed f32x2
#pragma unroll 2
        for (int j = 0; j < TJ; ++j) {
            const float* pj = sP  + j * TI;
            const float* wj = sWh + j * OUT_F;
            const ulonglong2 wA = *(const ulonglong2*)(wj + cA);
            const ulonglong2 wB = *(const ulonglong2*)(wj + cB);
            const float4 pA4 = *(const float4*)(pj + rA);
            const float4 pB4 = *(const float4*)(pj + rB);
            float pr[8] = {pA4.x, pA4.y, pA4.z, pA4.w, pB4.x, pB4.y, pB4.z, pB4.w};
#pragma unroll
            for (int r = 0; r < 8; ++r) {
                const unsigned long long pd = dup2(pr[r]);
                fma2(acc[r][0], pd, wA.x);
                fma2(acc[r][1], pd, wA.y);
                fma2(acc[r][2], pd, wB.x);
                fma2(acc[r][3], pd, wB.y);
            }
        }
    }

    // epilogue: raw partials
    const int pb = (split * HEADS + head) * NPAD;
    g_denp[pb + i0 + tid] = dsum;
#pragma unroll
    for (int r = 0; r < 8; ++r) {
        const int row = (r < 4) ? (rA + r) : (rB + r - 4);
        float* op = g_midp + (pb + i0 + row) * OUT_F;
        float2 v0 = upk(acc[r][0]), v1 = upk(acc[r][1]);
        *(float4*)(op + cA) = make_float4(v0.x, v0.y, v1.x, v1.y);
        v0 = upk(acc[r][2]); v1 = upk(acc[r][3]);
        *(float4*)(op + cB) = make_float4(v0.x, v0.y, v1.x, v1.y);
    }
}

// ---------------- kernel 4b: combine splits, normalize, ELU ----------------
__global__ void __launch_bounds__(256) k_fin() {
    const int t = blockIdx.x * 256 + threadIdx.x;   // [head][i][o] real rows
    const int o    = t & 63;
    const int i    = (t >> 6) % NTOT;
    const int head = t / (NTOT * OUT_F);
    float mid = 0.f, den = 0.f;
#pragma unroll
    for (int s = 0; s < KSPLIT; ++s) {
        const int pb = (s * HEADS + head) * NPAD + i;
        mid += g_midp[pb * OUT_F + o];
        den += g_denp[pb];
    }
    float x = mid / den;
    x = (x > 0.f) ? x : expm1f(x);
    g_x2[i * (HEADS * OUT_F) + head * OUT_F + o] = x;
}

// ---------------- kernel 5: log_softmax (128-wide) + permuted row write ----------------
__global__ void __launch_bounds__(256) k_lsm(float* __restrict__ out) {
    const int lane = threadIdx.x & 31;
    const int i = blockIdx.x * 8 + (threadIdx.x >> 5);
    float4 v = ((const float4*)(g_x2 + i * 128))[lane];
    float mx = fmaxf(fmaxf(v.x, v.y), fmaxf(v.z, v.w));
#pragma unroll
    for (int off = 16; off > 0; off >>= 1)
        mx = fmaxf(mx, __shfl_xor_sync(0xffffffffu, mx, off));
    float sum = __expf(v.x - mx) + __expf(v.y - mx) + __expf(v.z - mx) + __expf(v.w - mx);
#pragma unroll
    for (int off = 16; off > 0; off >>= 1)
        sum += __shfl_xor_sync(0xffffffffu, sum, off);
    const float lse = mx + logf(sum);
    // output row order: (x3 rows 5500:8000) | (x4 rows 0:3000) | (x5 rows 3000:5500)
    const int orow = (i < N1 + N2) ? (i + N3) : (i - (N1 + N2));
    float4 o = make_float4(v.x - lse, v.y - lse, v.z - lse, v.w - lse);
    ((float4*)out)[orow * 32 + lane] = o;
}

// ---------------- launch ----------------
extern "C" void kernel_launch(void* const* d_in, const int* in_sizes, int n_in,
                              void* d_out, int out_size) {
    const float* h   = (const float*)d_in[0];
    const int*   A1  = (const int*)d_in[1];
    const int*   A2  = (const int*)d_in[2];
    const int*   A3  = (const int*)d_in[3];
    const int*   A12 = (const int*)d_in[4];
    const int*   A13 = (const int*)d_in[5];
    const int*   A23 = (const int*)d_in[6];
    const int*   A21 = (const int*)d_in[7];
    const int*   A31 = (const int*)d_in[8];
    const int*   A32 = (const int*)d_in[9];
    const float* Ws  = (const float*)d_in[10];
    const float* ap  = (const float*)d_in[11];

    const int smem_att = (TJ * TI + TJ * OUT_F) * sizeof(float);   // 81920
    cudaFuncSetAttribute(k_att, cudaFuncAttributeMaxDynamicSharedMemorySize, smem_att);

    k_wh<<<(HEADS * NTOT * OUT_F) / 256, 256>>>(h, Ws);
    k_scal<<<(HEADS * NTOT + 255) / 256, 256>>>(ap);
    k_maskpack<<<NTOT, 256>>>(A1, A2, A3, A12, A13, A23, A21, A31, A32);
    k_att<<<dim3(IBLK, HEADS * KSPLIT), 256, smem_att>>>();
    k_fin<<<(HEADS * NTOT * OUT_F) / 256, 256>>>();
    k_lsm<<<NTOT / 8, 256>>>((float*)d_out);
}

// round 5
// speedup vs baseline: 3.3879x; 2.4577x over previous
#include <cuda_runtime.h>
#include <cuda_bf16.h>
#include <mma.h>
#include <math.h>
#include <stdint.h>

using namespace nvcuda;

// ---------------- problem constants ----------------
#define N1 3000
#define N2 2500
#define N3 2500
#define NTOT 8000
#define NPAD 8192
#define IN_F 128
#define OUT_F 64
#define HEADS 2
#define WORDS 250              // 8000/32 mask words per row

#define MROWS 128              // rows per k_att CTA
#define TJ 64                  // K per j-tile
#define NTILE_J (NTOT / TJ)    // 125

#define PSTR 72                // bf16 tile row stride (144B: conflict-free LDSM/STS)
#define CSTR 68                // f32 C tile row stride

// ---------------- device scratch ----------------
__device__ __nv_bfloat16 g_WhT[HEADS * OUT_F * NPAD];  // [head*64+o][n] bf16, 2MB
__device__ float    g_c [HEADS * NPAD];
__device__ float    g_E1[HEADS * NPAD];
__device__ float    g_E2[HEADS * NPAD];
__device__ float4   g_sff[HEADS * NPAD];               // {s, F1, F2, 0}
__device__ float    g_u [HEADS][2][IN_F];              // Ws @ a1|a2
__device__ unsigned g_mask[NPAD * WORDS];              // 8MB bitmask
__device__ float    g_x2[NTOT * HEADS * OUT_F];        // 4MB

// ---------------- helpers ----------------
static __device__ __forceinline__ unsigned long long dup2(float x) {
    unsigned long long r;
    asm("mov.b64 %0, {%1, %2};" : "=l"(r) : "f"(x), "f"(x));
    return r;
}
static __device__ __forceinline__ void fma2(unsigned long long &acc,
                                            unsigned long long a, unsigned long long b) {
    asm("fma.rn.f32x2 %0, %1, %2, %0;" : "+l"(acc) : "l"(a), "l"(b));
}
static __device__ __forceinline__ float2 upk(unsigned long long v) {
    float2 f;
    asm("mov.b64 {%0, %1}, %2;" : "=f"(f.x), "=f"(f.y) : "l"(v));
    return f;
}
static __device__ __forceinline__ unsigned cvt_bf16x2(float lo, float hi) {
    unsigned r;
    asm("cvt.rn.satfinite.bf16x2.f32 %0, %1, %2;" : "=r"(r) : "f"(hi), "f"(lo));
    return r;
}

// ---------------- kernel 0: u = Ws @ a  (512 dots of 64) ----------------
__global__ void __launch_bounds__(512) k_prep(const float* __restrict__ Ws,
                                              const float* __restrict__ ap) {
    const int t = threadIdx.x;
    const int hd = t >> 8, which = (t >> 7) & 1, f = t & 127;
    const float4* w = (const float4*)(Ws + hd * (IN_F * OUT_F) + f * OUT_F);
    const float4* a = (const float4*)(ap + hd * 2 * OUT_F + which * OUT_F);
    float acc = 0.f;
#pragma unroll
    for (int k = 0; k < OUT_F / 4; ++k) {
        float4 wv = w[k], av = a[k];
        acc += wv.x * av.x + wv.y * av.y + wv.z * av.z + wv.w * av.w;
    }
    g_u[hd][which][f] = acc;
}

// ---------------- kernel 1: per-node scalars via c = h.u1, s = h.u2 ----------------
__global__ void __launch_bounds__(256) k_scal(const float* __restrict__ h) {
    const int idx = blockIdx.x * 256 + threadIdx.x;
    if (idx >= HEADS * NTOT) return;
    const int hd = idx / NTOT, i = idx % NTOT;
    const int g = hd * NPAD + i;
    const float4* hr = (const float4*)(h + i * IN_F);
    const float4* u1 = (const float4*)(&g_u[hd][0][0]);
    const float4* u2 = (const float4*)(&g_u[hd][1][0]);
    float c = 0.f, s = 0.f;
#pragma unroll
    for (int k = 0; k < IN_F / 4; ++k) {
        float4 hv = hr[k], x = u1[k], y = u2[k];
        c += hv.x * x.x + hv.y * x.y + hv.z * x.z + hv.w * x.w;
        s += hv.x * y.x + hv.y * y.y + hv.z * y.z + hv.w * y.w;
    }
    g_c[g]  = c;
    g_E1[g] = __expf(c);
    g_E2[g] = __expf(0.2f * c);
    g_sff[g] = make_float4(s, __expf(s), __expf(0.2f * s), 0.f);
}

// ---------------- kernel 2: WhT (bf16, transposed) = (h @ Ws)^T ----------------
// grid 125, block 256, dyn smem: sh[128][68] + sW[128][128]
__global__ void __launch_bounds__(256) k_wh(const float* __restrict__ h,
                                            const float* __restrict__ Ws) {
    extern __shared__ float wsm[];
    float* sh = wsm;                 // [k][n pad 68]
    float* sW = wsm + 128 * 68;      // [k][ho=head*64+o]
    const int tid = threadIdx.x;
    const int n0 = blockIdx.x * 64;

    // stage Ws: global layout [hd][k][o4] flat == idx
#pragma unroll
    for (int e = 0; e < 16; ++e) {
        const int idx = tid + 256 * e;
        const int hd = idx >> 11, rem = idx & 2047, k = rem >> 4, o4 = rem & 15;
        float4 v = ((const float4*)Ws)[idx];
        *(float4*)&sW[k * 128 + hd * 64 + o4 * 4] = v;
    }
    // stage h transposed
#pragma unroll
    for (int e = 0; e < 8; ++e) {
        const int idx = tid + 256 * e;
        const int n = idx >> 5, k4 = idx & 31;
        float4 v = *(const float4*)(h + (n0 + n) * IN_F + k4 * 4);
        sh[(k4 * 4 + 0) * 68 + n] = v.x;
        sh[(k4 * 4 + 1) * 68 + n] = v.y;
        sh[(k4 * 4 + 2) * 68 + n] = v.z;
        sh[(k4 * 4 + 3) * 68 + n] = v.w;
    }
    __syncthreads();

    const int tx = tid & 15, ty = tid >> 4;     // 8 ho x 4 n per thread
    unsigned long long acc[4][4];
#pragma unroll
    for (int r = 0; r < 4; ++r)
#pragma unroll
        for (int c = 0; c < 4; ++c) acc[r][c] = 0ull;

#pragma unroll 4
    for (int k = 0; k < IN_F; ++k) {
        const float4 hv = *(const float4*)&sh[k * 68 + ty * 4];
        const ulonglong2 wA = *(const ulonglong2*)&sW[k * 128 + tx * 8];
        const ulonglong2 wB = *(const ulonglong2*)&sW[k * 128 + tx * 8 + 4];
        const float hr[4] = {hv.x, hv.y, hv.z, hv.w};
#pragma unroll
        for (int r = 0; r < 4; ++r) {
            const unsigned long long hd2 = dup2(hr[r]);
            fma2(acc[r][0], hd2, wA.x); fma2(acc[r][1], hd2, wA.y);
            fma2(acc[r][2], hd2, wB.x); fma2(acc[r][3], hd2, wB.y);
        }
    }

    // write transposed bf16: for each ho, 4 consecutive n
    float v[4][8];
#pragma unroll
    for (int r = 0; r < 4; ++r)
#pragma unroll
        for (int c = 0; c < 4; ++c) {
            float2 f = upk(acc[r][c]);
            v[r][2 * c] = f.x; v[r][2 * c + 1] = f.y;
        }
#pragma unroll
    for (int hh = 0; hh < 8; ++hh) {
        const int ho = tx * 8 + hh;
        unsigned u0 = cvt_bf16x2(v[0][hh], v[1][hh]);
        unsigned u1 = cvt_bf16x2(v[2][hh], v[3][hh]);
        *(uint2*)((char*)g_WhT + (ho * NPAD + n0 + ty * 4) * 2) = make_uint2(u0, u1);
    }
}

// ---------------- kernel 3: pack block-mask into bitmask ----------------
static __device__ __forceinline__ int mask_val(
    int i, int j,
    const int* __restrict__ A1,  const int* __restrict__ A2,  const int* __restrict__ A3,
    const int* __restrict__ A12, const int* __restrict__ A13, const int* __restrict__ A23,
    const int* __restrict__ A21, const int* __restrict__ A31, const int* __restrict__ A32) {
    if (i < N1) {
        if (j < N1) return A1[i * N1 + j];
        if (j < N1 + N2) return A12[i * N2 + (j - N1)];
        return A13[i * N3 + (j - N1 - N2)];
    } else if (i < N1 + N2) {
        int ii = i - N1;
        if (j < N1) return A21[ii * N1 + j];
        if (j < N1 + N2) return A2[ii * N2 + (j - N1)];
        return A23[ii * N3 + (j - N1 - N2)];
    } else {
        int ii = i - N1 - N2;
        if (j < N1) return A31[ii * N1 + j];
        if (j < N1 + N2) return A32[ii * N2 + (j - N1)];
        return A3[ii * N3 + (j - N1 - N2)];
    }
}

__global__ void __launch_bounds__(256) k_maskpack(
    const int* __restrict__ A1,  const int* __restrict__ A2,  const int* __restrict__ A3,
    const int* __restrict__ A12, const int* __restrict__ A13, const int* __restrict__ A23,
    const int* __restrict__ A21, const int* __restrict__ A31, const int* __restrict__ A32) {
    int row  = blockIdx.x;
    int warp = threadIdx.x >> 5;
    int lane = threadIdx.x & 31;
    int j0   = warp << 10;
    unsigned myword = 0;
#pragma unroll 1
    for (int it = 0; it < 32; ++it) {
        int j = j0 + (it << 5) + lane;
        int m = (j < NTOT) ? mask_val(row, j, A1, A2, A3, A12, A13, A23, A21, A31, A32) : 0;
        unsigned b = __ballot_sync(0xffffffffu, m > 0);
        if (lane == it) myword = b;
    }
    int w = (j0 >> 5) + lane;
    if (w < WORDS) g_mask[row * WORDS + w] = myword;
}

// ---------------- kernel 4: fused attention via WMMA bf16 (HMMA) ----------------
// grid (64, 2), 512 threads = 16 warps (8 row-blocks x 2 col-blocks).
// smem: sP [128][72] bf16 (18432B) + sB [64][72] bf16 (9216B); C aliases (34816B).
#define ATT_SMEM (MROWS * CSTR * 4)    // 34816 >= 18432 + 9216

__global__ void __launch_bounds__(512, 1) k_att() {
    extern __shared__ char dsm[];
    __nv_bfloat16* sP = (__nv_bfloat16*)dsm;                      // [128][PSTR]
    __nv_bfloat16* sB = (__nv_bfloat16*)(dsm + MROWS * PSTR * 2); // [64][PSTR]
    float* sC = (float*)dsm;                                      // alias, post-loop
    __shared__ float4 sSF[TJ];
    __shared__ float sDen[4][MROWS];

    const int head = blockIdx.y;
    const int i0   = blockIdx.x * MROWS;
    const int hb   = head * NPAD;
    const int tid  = threadIdx.x;
    const int wid  = tid >> 5;

    // p-gen role: row r, j-quarter q
    const int r = tid & 127;
    const int q = tid >> 7;
    const float c_i = g_c [hb + i0 + r];
    const float e1i = g_E1[hb + i0 + r];
    const float e2i = g_E2[hb + i0 + r];
    const unsigned* mrow = g_mask + (i0 + r) * WORDS;
    const int bitbase = (q & 1) * 16;
    const int jl0 = q * 16;

    // B-stage role: one 16B granule
    const int bo = tid >> 3, bg = tid & 7;
    const char* bsrc = (const char*)g_WhT + ((head * OUT_F + bo) * NPAD) * 2 + bg * 16;
    __nv_bfloat16* bdst = sB + bo * PSTR + bg * 8;

    // wmma role: warp tile 16 rows x 32 cols
    const int wy = wid & 7, wx = wid >> 3;
    wmma::fragment<wmma::accumulator, 16, 16, 16, float> c0, c1;
    wmma::fill_fragment(c0, 0.f);
    wmma::fill_fragment(c1, 0.f);

    float dsum = 0.f;

#pragma unroll 1
    for (int jt = 0; jt < NTILE_J; ++jt) {
        const int jbase = jt * TJ;
        __syncthreads();                       // prior compute done reading tiles

        *(uint4*)bdst = *(const uint4*)(bsrc + jbase * 2);
        if (tid < TJ) sSF[tid] = g_sff[hb + jbase + tid];
        __syncthreads();                       // sSF visible to p-gen

        // p-gen: 16 js -> 8 bf16x2, two STS.128 (conflict-free at 144B stride)
        {
            const unsigned mw = mrow[(jbase >> 5) + (q >> 1)];
            unsigned pk[8];
#pragma unroll
            for (int k2 = 0; k2 < 8; ++k2) {
                const float4 sf0 = sSF[jl0 + 2 * k2];
                const float4 sf1 = sSF[jl0 + 2 * k2 + 1];
                const float v0 = (c_i + sf0.x >= 0.f) ? e1i * sf0.y : e2i * sf0.z;
                const float v1 = (c_i + sf1.x >= 0.f) ? e1i * sf1.y : e2i * sf1.z;
                const float p0 = ((mw >> (bitbase + 2 * k2)) & 1u) ? v0 : 0.f;
                const float p1 = ((mw >> (bitbase + 2 * k2 + 1)) & 1u) ? v1 : 0.f;
                dsum += p0 + p1;
                pk[k2] = cvt_bf16x2(p0, p1);
            }
            uint4* d = (uint4*)(sP + r * PSTR + jl0);
            d[0] = make_uint4(pk[0], pk[1], pk[2], pk[3]);
            d[1] = make_uint4(pk[4], pk[5], pk[6], pk[7]);
        }
        __syncthreads();                       // tiles ready for compute

        // compute: 4 k-steps x (1 A frag, 2 B frags, 2 mma)
#pragma unroll
        for (int k = 0; k < 4; ++k) {
            wmma::fragment<wmma::matrix_a, 16, 16, 16, __nv_bfloat16, wmma::row_major> a;
            wmma::load_matrix_sync(a, sP + wy * 16 * PSTR + k * 16, PSTR);
            wmma::fragment<wmma::matrix_b, 16, 16, 16, __nv_bfloat16, wmma::col_major> b0, b1;
            wmma::load_matrix_sync(b0, sB + (wx * 32) * PSTR + k * 16, PSTR);
            wmma::load_matrix_sync(b1, sB + (wx * 32 + 16) * PSTR + k * 16, PSTR);
            wmma::mma_sync(c0, a, b0, c0);
            wmma::mma_sync(c1, a, b1, c1);
        }
    }

    sDen[q][r] = dsum;
    __syncthreads();                           // mainloop fully done; safe to alias

    wmma::store_matrix_sync(sC + wy * 16 * CSTR + wx * 32,      c0, CSTR, wmma::mem_row_major);
    wmma::store_matrix_sync(sC + wy * 16 * CSTR + wx * 32 + 16, c1, CSTR, wmma::mem_row_major);
    __syncthreads();

    // epilogue: normalize, ELU, write
    const int row = tid >> 2, cg = tid & 3;
    if (i0 + row < NTOT) {
        const float den = sDen[0][row] + sDen[1][row] + sDen[2][row] + sDen[3][row];
        const float inv = 1.f / den;
        const float* src = sC + row * CSTR + cg * 16;
        float* op = g_x2 + (i0 + row) * (HEADS * OUT_F) + head * OUT_F + cg * 16;
#pragma unroll
        for (int c4 = 0; c4 < 4; ++c4) {
            float4 v = *(const float4*)(src + c4 * 4);
            float x0 = v.x * inv, x1 = v.y * inv, x2 = v.z * inv, x3 = v.w * inv;
            x0 = (x0 > 0.f) ? x0 : expm1f(x0);
            x1 = (x1 > 0.f) ? x1 : expm1f(x1);
            x2 = (x2 > 0.f) ? x2 : expm1f(x2);
            x3 = (x3 > 0.f) ? x3 : expm1f(x3);
            *(float4*)(op + c4 * 4) = make_float4(x0, x1, x2, x3);
        }
    }
}

// ---------------- kernel 5: log_softmax (128-wide) + permuted row write ----------------
__global__ void __launch_bounds__(256) k_lsm(float* __restrict__ out) {
    const int lane = threadIdx.x & 31;
    const int i = blockIdx.x * 8 + (threadIdx.x >> 5);
    float4 v = ((const float4*)(g_x2 + i * 128))[lane];
    float mx = fmaxf(fmaxf(v.x, v.y), fmaxf(v.z, v.w));
#pragma unroll
    for (int off = 16; off > 0; off >>= 1)
        mx = fmaxf(mx, __shfl_xor_sync(0xffffffffu, mx, off));
    float sum = __expf(v.x - mx) + __expf(v.y - mx) + __expf(v.z - mx) + __expf(v.w - mx);
#pragma unroll
    for (int off = 16; off > 0; off >>= 1)
        sum += __shfl_xor_sync(0xffffffffu, sum, off);
    const float lse = mx + logf(sum);
    const int orow = (i < N1 + N2) ? (i + N3) : (i - (N1 + N2));
    float4 o = make_float4(v.x - lse, v.y - lse, v.z - lse, v.w - lse);
    ((float4*)out)[orow * 32 + lane] = o;
}

// ---------------- launch ----------------
extern "C" void kernel_launch(void* const* d_in, const int* in_sizes, int n_in,
                              void* d_out, int out_size) {
    const float* h   = (const float*)d_in[0];
    const int*   A1  = (const int*)d_in[1];
    const int*   A2  = (const int*)d_in[2];
    const int*   A3  = (const int*)d_in[3];
    const int*   A12 = (const int*)d_in[4];
    const int*   A13 = (const int*)d_in[5];
    const int*   A23 = (const int*)d_in[6];
    const int*   A21 = (const int*)d_in[7];
    const int*   A31 = (const int*)d_in[8];
    const int*   A32 = (const int*)d_in[9];
    const float* Ws  = (const float*)d_in[10];
    const float* ap  = (const float*)d_in[11];

    const int wh_smem = (128 * 68 + 128 * 128) * sizeof(float);   // 100352
    cudaFuncSetAttribute(k_wh,  cudaFuncAttributeMaxDynamicSharedMemorySize, wh_smem);
    cudaFuncSetAttribute(k_att, cudaFuncAttributeMaxDynamicSharedMemorySize, ATT_SMEM);

    k_prep<<<1, 512>>>(Ws, ap);
    k_scal<<<(HEADS * NTOT + 255) / 256, 256>>>(h);
    k_wh<<<NTOT / 64, 256, wh_smem>>>(h, Ws);
    k_maskpack<<<NTOT, 256>>>(A1, A2, A3, A12, A13, A23, A21, A31, A32);
    k_att<<<dim3(NPAD / MROWS, HEADS), 512, ATT_SMEM>>>();
    k_lsm<<<NTOT / 8, 256>>>((float*)d_out);
}

// round 6
// speedup vs baseline: 5.5339x; 1.6334x over previous
#include <cuda_runtime.h>
#include <cuda_bf16.h>
#include <mma.h>
#include <math.h>
#include <stdint.h>

using namespace nvcuda;

// ---------------- problem constants ----------------
#define N1 3000
#define N2 2500
#define N3 2500
#define NTOT 8000
#define NPAD 8192
#define IN_F 128
#define OUT_F 64
#define HEADS 2
#define WORDS 250              // 8000/32 mask words per row

#define MROWS 128              // rows per k_att CTA
#define TJ 64                  // K per j-tile
#define NTILE_J (NTOT / TJ)    // 125

#define PSTR 72                // bf16 tile row stride (144B: conflict-free LDSM/STS)
#define CSTR 68                // f32 C tile row stride

// ---------------- device scratch ----------------
__device__ __nv_bfloat16 g_WhT[HEADS * OUT_F * NPAD];  // [head*64+o][n] bf16, 2MB
__device__ float    g_c [HEADS * NPAD];
__device__ float    g_E1[HEADS * NPAD];
__device__ float    g_E2[HEADS * NPAD];
__device__ float4   g_sff[HEADS * NPAD];               // {s, F1, F2, 0}
__device__ float    g_u [HEADS][2][IN_F];              // Ws @ a1|a2
__device__ unsigned g_mask[NPAD * WORDS];              // 8MB bitmask
__device__ float    g_x2[NTOT * HEADS * OUT_F];        // 4MB

// ---------------- helpers ----------------
static __device__ __forceinline__ unsigned long long dup2(float x) {
    unsigned long long r;
    asm("mov.b64 %0, {%1, %2};" : "=l"(r) : "f"(x), "f"(x));
    return r;
}
static __device__ __forceinline__ void fma2(unsigned long long &acc,
                                            unsigned long long a, unsigned long long b) {
    asm("fma.rn.f32x2 %0, %1, %2, %0;" : "+l"(acc) : "l"(a), "l"(b));
}
static __device__ __forceinline__ float2 upk(unsigned long long v) {
    float2 f;
    asm("mov.b64 {%0, %1}, %2;" : "=f"(f.x), "=f"(f.y) : "l"(v));
    return f;
}
static __device__ __forceinline__ unsigned cvt_bf16x2(float lo, float hi) {
    unsigned r;
    asm("cvt.rn.satfinite.bf16x2.f32 %0, %1, %2;" : "=r"(r) : "f"(hi), "f"(lo));
    return r;
}

// ---------------- kernel 0: u = Ws @ a  (512 dots of 64) ----------------
__global__ void __launch_bounds__(512) k_prep(const float* __restrict__ Ws,
                                              const float* __restrict__ ap) {
    const int t = threadIdx.x;
    const int hd = t >> 8, which = (t >> 7) & 1, f = t & 127;
    const float4* w = (const float4*)(Ws + hd * (IN_F * OUT_F) + f * OUT_F);
    const float4* a = (const float4*)(ap + hd * 2 * OUT_F + which * OUT_F);
    float acc = 0.f;
#pragma unroll
    for (int k = 0; k < OUT_F / 4; ++k) {
        float4 wv = w[k], av = a[k];
        acc += wv.x * av.x + wv.y * av.y + wv.z * av.z + wv.w * av.w;
    }
    g_u[hd][which][f] = acc;
}

// ---------------- kernel 1: per-node scalars via c = h.u1, s = h.u2 ----------------
__global__ void __launch_bounds__(256) k_scal(const float* __restrict__ h) {
    const int idx = blockIdx.x * 256 + threadIdx.x;
    if (idx >= HEADS * NTOT) return;
    const int hd = idx / NTOT, i = idx % NTOT;
    const int g = hd * NPAD + i;
    const float4* hr = (const float4*)(h + i * IN_F);
    const float4* u1 = (const float4*)(&g_u[hd][0][0]);
    const float4* u2 = (const float4*)(&g_u[hd][1][0]);
    float c = 0.f, s = 0.f;
#pragma unroll
    for (int k = 0; k < IN_F / 4; ++k) {
        float4 hv = hr[k], x = u1[k], y = u2[k];
        c += hv.x * x.x + hv.y * x.y + hv.z * x.z + hv.w * x.w;
        s += hv.x * y.x + hv.y * y.y + hv.z * y.z + hv.w * y.w;
    }
    g_c[g]  = c;
    g_E1[g] = __expf(c);
    g_E2[g] = __expf(0.2f * c);
    g_sff[g] = make_float4(s, __expf(s), __expf(0.2f * s), 0.f);
}

// ---------------- kernel 2: WhT (bf16, transposed) = (h @ Ws)^T ----------------
// grid 125, block 256, dyn smem: sh[128][68] + sW[128][128]
__global__ void __launch_bounds__(256) k_wh(const float* __restrict__ h,
                                            const float* __restrict__ Ws) {
    extern __shared__ float wsm[];
    float* sh = wsm;                 // [k][n pad 68]
    float* sW = wsm + 128 * 68;      // [k][ho=head*64+o]
    const int tid = threadIdx.x;
    const int n0 = blockIdx.x * 64;

    // stage Ws: global layout [hd][k][o4] flat == idx
#pragma unroll
    for (int e = 0; e < 16; ++e) {
        const int idx = tid + 256 * e;
        const int hd = idx >> 11, rem = idx & 2047, k = rem >> 4, o4 = rem & 15;
        float4 v = ((const float4*)Ws)[idx];
        *(float4*)&sW[k * 128 + hd * 64 + o4 * 4] = v;
    }
    // stage h transposed
#pragma unroll
    for (int e = 0; e < 8; ++e) {
        const int idx = tid + 256 * e;
        const int n = idx >> 5, k4 = idx & 31;
        float4 v = *(const float4*)(h + (n0 + n) * IN_F + k4 * 4);
        sh[(k4 * 4 + 0) * 68 + n] = v.x;
        sh[(k4 * 4 + 1) * 68 + n] = v.y;
        sh[(k4 * 4 + 2) * 68 + n] = v.z;
        sh[(k4 * 4 + 3) * 68 + n] = v.w;
    }
    __syncthreads();

    const int tx = tid & 15, ty = tid >> 4;     // 8 ho x 4 n per thread
    unsigned long long acc[4][4];
#pragma unroll
    for (int r = 0; r < 4; ++r)
#pragma unroll
        for (int c = 0; c < 4; ++c) acc[r][c] = 0ull;

#pragma unroll 4
    for (int k = 0; k < IN_F; ++k) {
        const float4 hv = *(const float4*)&sh[k * 68 + ty * 4];
        const ulonglong2 wA = *(const ulonglong2*)&sW[k * 128 + tx * 8];
        const ulonglong2 wB = *(const ulonglong2*)&sW[k * 128 + tx * 8 + 4];
        const float hr[4] = {hv.x, hv.y, hv.z, hv.w};
#pragma unroll
        for (int r = 0; r < 4; ++r) {
            const unsigned long long hd2 = dup2(hr[r]);
            fma2(acc[r][0], hd2, wA.x); fma2(acc[r][1], hd2, wA.y);
            fma2(acc[r][2], hd2, wB.x); fma2(acc[r][3], hd2, wB.y);
        }
    }

    // write transposed bf16: for each ho, 4 consecutive n
    float v[4][8];
#pragma unroll
    for (int r = 0; r < 4; ++r)
#pragma unroll
        for (int c = 0; c < 4; ++c) {
            float2 f = upk(acc[r][c]);
            v[r][2 * c] = f.x; v[r][2 * c + 1] = f.y;
        }
#pragma unroll
    for (int hh = 0; hh < 8; ++hh) {
        const int ho = tx * 8 + hh;
        unsigned u0 = cvt_bf16x2(v[0][hh], v[1][hh]);
        unsigned u1 = cvt_bf16x2(v[2][hh], v[3][hh]);
        *(uint2*)((char*)g_WhT + (ho * NPAD + n0 + ty * 4) * 2) = make_uint2(u0, u1);
    }
}

// ---------------- kernel 3: pack block-mask into bitmask ----------------
// int4 vectorized, MLP=8, no ballot (nibble + REDUX.OR over 8-lane groups).
static __device__ __forceinline__ int4 mask4(
    int i, int j4,
    const int* __restrict__ A1,  const int* __restrict__ A2,  const int* __restrict__ A3,
    const int* __restrict__ A12, const int* __restrict__ A13, const int* __restrict__ A23,
    const int* __restrict__ A21, const int* __restrict__ A31, const int* __restrict__ A32) {
    const int j = j4 * 4;
    if (i < N1) {
        if (j < N1) return *(const int4*)(A1 + i * N1 + j);
        if (j < N1 + N2) return *(const int4*)(A12 + i * N2 + (j - N1));
        return *(const int4*)(A13 + i * N3 + (j - N1 - N2));
    } else if (i < N1 + N2) {
        const int ii = i - N1;
        if (j < N1) return *(const int4*)(A21 + ii * N1 + j);
        if (j < N1 + N2) return *(const int4*)(A2 + ii * N2 + (j - N1));
        return *(const int4*)(A23 + ii * N3 + (j - N1 - N2));
    } else {
        const int ii = i - N1 - N2;
        if (j < N1) return *(const int4*)(A31 + ii * N1 + j);
        if (j < N1 + N2) return *(const int4*)(A32 + ii * N2 + (j - N1));
        return *(const int4*)(A3 + ii * N3 + (j - N1 - N2));
    }
}

__global__ void __launch_bounds__(256) k_maskpack(
    const int* __restrict__ A1,  const int* __restrict__ A2,  const int* __restrict__ A3,
    const int* __restrict__ A12, const int* __restrict__ A13, const int* __restrict__ A23,
    const int* __restrict__ A21, const int* __restrict__ A31, const int* __restrict__ A32) {
    const int row  = blockIdx.x;
    const int t    = threadIdx.x;
    const int lane = t & 31;
    const unsigned gmask = 0xFFu << ((lane >> 3) << 3);
    const int shift = (lane & 7) * 4;

    int4 v[8];
#pragma unroll
    for (int it = 0; it < 8; ++it) {
        const int idx4 = it * 256 + t;           // int4 index within row (0..1999)
        if (idx4 < 2000)
            v[it] = mask4(row, idx4, A1, A2, A3, A12, A13, A23, A21, A31, A32);
    }
#pragma unroll
    for (int it = 0; it < 8; ++it) {
        const int idx4 = it * 256 + t;
        if (idx4 < 2000) {
            const int4 a = v[it];
            unsigned nib = (unsigned)(a.x > 0) | ((unsigned)(a.y > 0) << 1)
                         | ((unsigned)(a.z > 0) << 2) | ((unsigned)(a.w > 0) << 3);
            const unsigned word = __reduce_or_sync(gmask, nib << shift);
            if ((lane & 7) == 0)
                g_mask[row * WORDS + (idx4 >> 3)] = word;
        }
    }
}

// ---------------- kernel 4: fused attention via WMMA bf16 (HMMA) ----------------
// grid (64, 2), 512 threads = 16 warps (8 row-blocks x 2 col-blocks).
// smem: sP [128][72] bf16 (18432B) + sB [64][72] bf16 (9216B); C aliases (34816B).
// Per-tile global inputs (mask word, sff float4, B granule) register-prefetched
// one tile ahead so WMMA + barriers cover their latency.
#define ATT_SMEM (MROWS * CSTR * 4)    // 34816 >= 18432 + 9216

__global__ void __launch_bounds__(512, 1) k_att() {
    extern __shared__ char dsm[];
    __nv_bfloat16* sP = (__nv_bfloat16*)dsm;                      // [128][PSTR]
    __nv_bfloat16* sB = (__nv_bfloat16*)(dsm + MROWS * PSTR * 2); // [64][PSTR]
    float* sC = (float*)dsm;                                      // alias, post-loop
    __shared__ float4 sSF[TJ];
    __shared__ float sDen[4][MROWS];

    const int head = blockIdx.y;
    const int i0   = blockIdx.x * MROWS;
    const int hb   = head * NPAD;
    const int tid  = threadIdx.x;
    const int wid  = tid >> 5;

    // p-gen role: row r, j-quarter q
    const int r = tid & 127;
    const int q = tid >> 7;
    const float c_i = g_c [hb + i0 + r];
    const float e1i = g_E1[hb + i0 + r];
    const float e2i = g_E2[hb + i0 + r];
    const unsigned* mrow = g_mask + (i0 + r) * WORDS;
    const int bitbase = (q & 1) * 16;
    const int jl0 = q * 16;

    // B-stage role: one 16B granule
    const int bo = tid >> 3, bg = tid & 7;
    const char* bsrc = (const char*)g_WhT + ((head * OUT_F + bo) * NPAD) * 2 + bg * 16;
    __nv_bfloat16* bdst = sB + bo * PSTR + bg * 8;

    // wmma role: warp tile 16 rows x 32 cols
    const int wy = wid & 7, wx = wid >> 3;
    wmma::fragment<wmma::accumulator, 16, 16, 16, float> c0, c1;
    wmma::fill_fragment(c0, 0.f);
    wmma::fill_fragment(c1, 0.f);

    float dsum = 0.f;

    // prefetch tile 0
    uint4 nbg = *(const uint4*)bsrc;
    float4 nsf;
    if (tid < TJ) nsf = g_sff[hb + tid];
    unsigned nmw = mrow[q >> 1];

#pragma unroll 1
    for (int jt = 0; jt < NTILE_J; ++jt) {
        __syncthreads();                       // prior compute done reading tiles

        *(uint4*)bdst = nbg;
        if (tid < TJ) sSF[tid] = nsf;
        const unsigned mw = nmw;
        __syncthreads();                       // sSF/B visible

        // p-gen: 16 js -> 8 bf16x2, two STS.128 (conflict-free at 144B stride)
        {
            unsigned pk[8];
#pragma unroll
            for (int k2 = 0; k2 < 8; ++k2) {
                const float4 sf0 = sSF[jl0 + 2 * k2];
                const float4 sf1 = sSF[jl0 + 2 * k2 + 1];
                const float v0 = (c_i + sf0.x >= 0.f) ? e1i * sf0.y : e2i * sf0.z;
                const float v1 = (c_i + sf1.x >= 0.f) ? e1i * sf1.y : e2i * sf1.z;
                const float p0 = ((mw >> (bitbase + 2 * k2)) & 1u) ? v0 : 0.f;
                const float p1 = ((mw >> (bitbase + 2 * k2 + 1)) & 1u) ? v1 : 0.f;
                dsum += p0 + p1;
                pk[k2] = cvt_bf16x2(p0, p1);
            }
            uint4* d = (uint4*)(sP + r * PSTR + jl0);
            d[0] = make_uint4(pk[0], pk[1], pk[2], pk[3]);
            d[1] = make_uint4(pk[4], pk[5], pk[6], pk[7]);
        }

        // prefetch tile jt+1 (latency covered by wmma + barriers)
        if (jt + 1 < NTILE_J) {
            const int jb = (jt + 1) * TJ;
            nbg = *(const uint4*)(bsrc + jb * 2);
            if (tid < TJ) nsf = g_sff[hb + jb + tid];
            nmw = mrow[(jb >> 5) + (q >> 1)];
        }
        __syncthreads();                       // tiles ready for compute

        // compute: 4 k-steps x (1 A frag, 2 B frags, 2 mma)
#pragma unroll
        for (int k = 0; k < 4; ++k) {
            wmma::fragment<wmma::matrix_a, 16, 16, 16, __nv_bfloat16, wmma::row_major> a;
            wmma::load_matrix_sync(a, sP + wy * 16 * PSTR + k * 16, PSTR);
            wmma::fragment<wmma::matrix_b, 16, 16, 16, __nv_bfloat16, wmma::col_major> b0, b1;
            wmma::load_matrix_sync(b0, sB + (wx * 32) * PSTR + k * 16, PSTR);
            wmma::load_matrix_sync(b1, sB + (wx * 32 + 16) * PSTR + k * 16, PSTR);
            wmma::mma_sync(c0, a, b0, c0);
            wmma::mma_sync(c1, a, b1, c1);
        }
    }

    sDen[q][r] = dsum;
    __syncthreads();                           // mainloop fully done; safe to alias

    wmma::store_matrix_sync(sC + wy * 16 * CSTR + wx * 32,      c0, CSTR, wmma::mem_row_major);
    wmma::store_matrix_sync(sC + wy * 16 * CSTR + wx * 32 + 16, c1, CSTR, wmma::mem_row_major);
    __syncthreads();

    // epilogue: normalize, ELU, write
    const int row = tid >> 2, cg = tid & 3;
    if (i0 + row < NTOT) {
        const float den = sDen[0][row] + sDen[1][row] + sDen[2][row] + sDen[3][row];
        const float inv = 1.f / den;
        const float* src = sC + row * CSTR + cg * 16;
        float* op = g_x2 + (i0 + row) * (HEADS * OUT_F) + head * OUT_F + cg * 16;
#pragma unroll
        for (int c4 = 0; c4 < 4; ++c4) {
            float4 v = *(const float4*)(src + c4 * 4);
            float x0 = v.x * inv, x1 = v.y * inv, x2 = v.z * inv, x3 = v.w * inv;
            x0 = (x0 > 0.f) ? x0 : expm1f(x0);
            x1 = (x1 > 0.f) ? x1 : expm1f(x1);
            x2 = (x2 > 0.f) ? x2 : expm1f(x2);
            x3 = (x3 > 0.f) ? x3 : expm1f(x3);
            *(float4*)(op + c4 * 4) = make_float4(x0, x1, x2, x3);
        }
    }
}

// ---------------- kernel 5: log_softmax (128-wide) + permuted row write ----------------
__global__ void __launch_bounds__(256) k_lsm(float* __restrict__ out) {
    const int lane = threadIdx.x & 31;
    const int i = blockIdx.x * 8 + (threadIdx.x >> 5);
    float4 v = ((const float4*)(g_x2 + i * 128))[lane];
    float mx = fmaxf(fmaxf(v.x, v.y), fmaxf(v.z, v.w));
#pragma unroll
    for (int off = 16; off > 0; off >>= 1)
        mx = fmaxf(mx, __shfl_xor_sync(0xffffffffu, mx, off));
    float sum = __expf(v.x - mx) + __expf(v.y - mx) + __expf(v.z - mx) + __expf(v.w - mx);
#pragma unroll
    for (int off = 16; off > 0; off >>= 1)
        sum += __shfl_xor_sync(0xffffffffu, sum, off);
    const float lse = mx + logf(sum);
    const int orow = (i < N1 + N2) ? (i + N3) : (i - (N1 + N2));
    float4 o = make_float4(v.x - lse, v.y - lse, v.z - lse, v.w - lse);
    ((float4*)out)[orow * 32 + lane] = o;
}

// ---------------- launch ----------------
extern "C" void kernel_launch(void* const* d_in, const int* in_sizes, int n_in,
                              void* d_out, int out_size) {
    const float* h   = (const float*)d_in[0];
    const int*   A1  = (const int*)d_in[1];
    const int*   A2  = (const int*)d_in[2];
    const int*   A3  = (const int*)d_in[3];
    const int*   A12 = (const int*)d_in[4];
    const int*   A13 = (const int*)d_in[5];
    const int*   A23 = (const int*)d_in[6];
    const int*   A21 = (const int*)d_in[7];
    const int*   A31 = (const int*)d_in[8];
    const int*   A32 = (const int*)d_in[9];
    const float* Ws  = (const float*)d_in[10];
    const float* ap  = (const float*)d_in[11];

    const int wh_smem = (128 * 68 + 128 * 128) * sizeof(float);   // 100352
    cudaFuncSetAttribute(k_wh,  cudaFuncAttributeMaxDynamicSharedMemorySize, wh_smem);
    cudaFuncSetAttribute(k_att, cudaFuncAttributeMaxDynamicSharedMemorySize, ATT_SMEM);

    k_prep<<<1, 512>>>(Ws, ap);
    k_scal<<<(HEADS * NTOT + 255) / 256, 256>>>(h);
    k_wh<<<NTOT / 64, 256, wh_smem>>>(h, Ws);
    k_maskpack<<<NTOT, 256>>>(A1, A2, A3, A12, A13, A23, A21, A31, A32);
    k_att<<<dim3(NPAD / MROWS, HEADS), 512, ATT_SMEM>>>();
    k_lsm<<<NTOT / 8, 256>>>((float*)d_out);
}